// round 1
// baseline (speedup 1.0000x reference)
#include <cuda_runtime.h>
#include <math.h>

#define B_  2
#define T_  2048
#define C_  2048
#define QH  32
#define KVH 8
#define HD  64
#define NG  4
#define KVC (KVH*HD)   // 512

// Scratch (allocation-free rule: __device__ globals)
__device__ float g_q  [(size_t)B_*T_*C_];    // [b*T+t][h*64+d]
__device__ float g_k  [(size_t)B_*T_*KVC];   // [b*T+t][kvh*64+d]
__device__ float g_v  [(size_t)B_*T_*KVC];
__device__ float g_att[(size_t)B_*T_*C_];

// ---------------------------------------------------------------------------
// C[M,N] = A[M,K] @ W[N,K]^T   (row-major, M%128==0, N%128==0, K%8==0)
// 128x128 tile, 256 threads, 8x8 acc per thread, K-step 8.
// ---------------------------------------------------------------------------
__global__ __launch_bounds__(256) void gemm_tn(const float* __restrict__ A,
                                               const float* __restrict__ W,
                                               float* __restrict__ Cm,
                                               int M, int N, int K) {
    __shared__ float As[8][132];   // [k][m], pad: 132*4B = 16B-aligned rows
    __shared__ float Bs[8][132];   // [k][n]
    const int m0 = blockIdx.y * 128;
    const int n0 = blockIdx.x * 128;
    const int tid = threadIdx.x;
    const int tm = tid & 15;        // 0..15 -> 8 rows each
    const int tn = tid >> 4;        // 0..15 -> 8 cols each
    const int lrow = tid >> 1;      // 0..127
    const int lkq  = tid & 1;       // 0..1  -> float4 within 8-wide k

    float acc[8][8];
#pragma unroll
    for (int i = 0; i < 8; i++)
#pragma unroll
        for (int j = 0; j < 8; j++) acc[i][j] = 0.f;

    const float* Ald = A + (size_t)(m0 + lrow) * K + lkq * 4;
    const float* Wld = W + (size_t)(n0 + lrow) * K + lkq * 4;

    for (int k0 = 0; k0 < K; k0 += 8) {
        float4 a = *(const float4*)(Ald + k0);
        float4 b = *(const float4*)(Wld + k0);
        As[lkq*4+0][lrow] = a.x; As[lkq*4+1][lrow] = a.y;
        As[lkq*4+2][lrow] = a.z; As[lkq*4+3][lrow] = a.w;
        Bs[lkq*4+0][lrow] = b.x; Bs[lkq*4+1][lrow] = b.y;
        Bs[lkq*4+2][lrow] = b.z; Bs[lkq*4+3][lrow] = b.w;
        __syncthreads();
#pragma unroll
        for (int kk = 0; kk < 8; kk++) {
            float ar[8], br[8];
            *(float4*)&ar[0] = *(const float4*)&As[kk][tm*8];
            *(float4*)&ar[4] = *(const float4*)&As[kk][tm*8+4];
            *(float4*)&br[0] = *(const float4*)&Bs[kk][tn*8];
            *(float4*)&br[4] = *(const float4*)&Bs[kk][tn*8+4];
#pragma unroll
            for (int i = 0; i < 8; i++)
#pragma unroll
                for (int j = 0; j < 8; j++) acc[i][j] += ar[i] * br[j];
        }
        __syncthreads();
    }

#pragma unroll
    for (int i = 0; i < 8; i++) {
        float* cp = Cm + (size_t)(m0 + tm*8 + i) * N + n0 + tn*8;
        float4 c0, c1;
        c0.x = acc[i][0]; c0.y = acc[i][1]; c0.z = acc[i][2]; c0.w = acc[i][3];
        c1.x = acc[i][4]; c1.y = acc[i][5]; c1.z = acc[i][6]; c1.w = acc[i][7];
        *(float4*)cp       = c0;
        *(float4*)(cp + 4) = c1;
    }
}

// ---------------------------------------------------------------------------
// Flash attention: one block per (b, h, 64-row q tile). 256 threads.
// Thread t owns row r = t/4, and a 16-wide slice (quad = t%4) of both the
// score columns (c0..c0+15) and the output dims (d0..d0+15).
// Online softmax state (m, l) replicated across the 4 threads of a row via
// quad shfl reductions.
// SMEM: Qs[64][68], Kst[64][68] (K transposed: [d][c]), Vs[64][68], Ps[64][68]
// ---------------------------------------------------------------------------
#define APAD 68
#define ATT_SMEM (4 * 64 * APAD * 4)

__global__ __launch_bounds__(256) void attn_kernel() {
    extern __shared__ float sm[];
    float* Qs  = sm;
    float* Kst = sm + 64 * APAD;
    float* Vs  = sm + 2 * 64 * APAD;
    float* Ps  = sm + 3 * 64 * APAD;

    const int qt  = blockIdx.x;
    const int h   = blockIdx.y;
    const int b   = blockIdx.z;
    const int kvh = h >> 2;                 // h / NG
    const int tid = threadIdx.x;
    const int r    = tid >> 2;
    const int quad = tid & 3;
    const int c0 = quad * 16;
    const int d0 = quad * 16;
    const int qi = qt * 64 + r;

    // Load Q tile (64 rows x 64 dims). Covered by the sync inside the k-loop.
    for (int idx = tid; idx < 1024; idx += 256) {
        int row = idx >> 4, dq = idx & 15;
        float4 v = *(const float4*)&g_q[(size_t)(b*T_ + qt*64 + row) * C_ + h*HD + dq*4];
        *(float4*)&Qs[row*APAD + dq*4] = v;
    }

    float m = -INFINITY, l = 0.f;
    float acc[16];
#pragma unroll
    for (int i = 0; i < 16; i++) acc[i] = 0.f;

    for (int kt = 0; kt <= qt; kt++) {
        // Load K (transposed into [d][c]) and V ([c][d])
        for (int idx = tid; idx < 1024; idx += 256) {
            int row = idx >> 4, dq = idx & 15;
            size_t base = (size_t)(b*T_ + kt*64 + row) * KVC + kvh*HD + dq*4;
            float4 kv = *(const float4*)&g_k[base];
            Kst[(dq*4+0)*APAD + row] = kv.x;
            Kst[(dq*4+1)*APAD + row] = kv.y;
            Kst[(dq*4+2)*APAD + row] = kv.z;
            Kst[(dq*4+3)*APAD + row] = kv.w;
            float4 vv = *(const float4*)&g_v[base];
            *(float4*)&Vs[row*APAD + dq*4] = vv;
        }
        __syncthreads();

        // S = Q @ K^T  (thread computes s[r][c0..c0+15])
        float s[16];
#pragma unroll
        for (int j = 0; j < 16; j++) s[j] = 0.f;
#pragma unroll
        for (int d4 = 0; d4 < 16; d4++) {
            float4 q4 = *(const float4*)&Qs[r*APAD + d4*4];
            float qv[4] = {q4.x, q4.y, q4.z, q4.w};
#pragma unroll
            for (int dd = 0; dd < 4; dd++) {
                const float* kp = &Kst[(d4*4+dd)*APAD + c0];
                float4 ka = *(const float4*)(kp);
                float4 kb = *(const float4*)(kp+4);
                float4 kc = *(const float4*)(kp+8);
                float4 kd = *(const float4*)(kp+12);
                float q = qv[dd];
                s[0]+=q*ka.x; s[1]+=q*ka.y; s[2]+=q*ka.z; s[3]+=q*ka.w;
                s[4]+=q*kb.x; s[5]+=q*kb.y; s[6]+=q*kb.z; s[7]+=q*kb.w;
                s[8]+=q*kc.x; s[9]+=q*kc.y; s[10]+=q*kc.z; s[11]+=q*kc.w;
                s[12]+=q*kd.x; s[13]+=q*kd.y; s[14]+=q*kd.z; s[15]+=q*kd.w;
            }
        }

        // scale + causal mask (finite sentinel avoids inf-inf)
        const float sc = 0.125f;   // 1/sqrt(64)
        float mt = -1e30f;
#pragma unroll
        for (int j = 0; j < 16; j++) {
            int kj = kt*64 + c0 + j;
            s[j] = (kj <= qi) ? s[j] * sc : -1e30f;
            mt = fmaxf(mt, s[j]);
        }
        // row reduction across the 4 quad lanes (consecutive lanes in warp)
        mt = fmaxf(mt, __shfl_xor_sync(0xffffffffu, mt, 1));
        mt = fmaxf(mt, __shfl_xor_sync(0xffffffffu, mt, 2));
        float m_new = fmaxf(m, mt);
        float corr = __expf(m - m_new);    // first tile: exp(-inf)=0
        float psum = 0.f;
#pragma unroll
        for (int j = 0; j < 16; j++) {
            float p = __expf(s[j] - m_new);  // masked -> exp(~-1e30) = 0
            psum += p;
            Ps[r*APAD + c0 + j] = p;
        }
        psum += __shfl_xor_sync(0xffffffffu, psum, 1);
        psum += __shfl_xor_sync(0xffffffffu, psum, 2);
        l = l * corr + psum;
        m = m_new;
#pragma unroll
        for (int i = 0; i < 16; i++) acc[i] *= corr;
        __syncthreads();

        // O += P @ V  (thread accumulates o[r][d0..d0+15])
#pragma unroll 4
        for (int c = 0; c < 64; c++) {
            float p = Ps[r*APAD + c];
            const float* vp = &Vs[c*APAD + d0];
            float4 va = *(const float4*)(vp);
            float4 vb = *(const float4*)(vp+4);
            float4 vc = *(const float4*)(vp+8);
            float4 vd = *(const float4*)(vp+12);
            acc[0]+=p*va.x; acc[1]+=p*va.y; acc[2]+=p*va.z; acc[3]+=p*va.w;
            acc[4]+=p*vb.x; acc[5]+=p*vb.y; acc[6]+=p*vb.z; acc[7]+=p*vb.w;
            acc[8]+=p*vc.x; acc[9]+=p*vc.y; acc[10]+=p*vc.z; acc[11]+=p*vc.w;
            acc[12]+=p*vd.x; acc[13]+=p*vd.y; acc[14]+=p*vd.z; acc[15]+=p*vd.w;
        }
        __syncthreads();   // protect Kst/Vs/Ps before next tile's loads
    }

    float inv = 1.f / l;
    float* op = &g_att[(size_t)(b*T_ + qi) * C_ + h*HD + d0];
#pragma unroll
    for (int i = 0; i < 16; i += 4) {
        float4 o;
        o.x = acc[i+0]*inv; o.y = acc[i+1]*inv;
        o.z = acc[i+2]*inv; o.w = acc[i+3]*inv;
        *(float4*)(op + i) = o;
    }
}

// ---------------------------------------------------------------------------
extern "C" void kernel_launch(void* const* d_in, const int* in_sizes, int n_in,
                              void* d_out, int out_size) {
    const float* x  = (const float*)d_in[0];
    const float* wq = (const float*)d_in[1];
    const float* wk = (const float*)d_in[2];
    const float* wv = (const float*)d_in[3];
    const float* wo = (const float*)d_in[4];
    float* out = (float*)d_out;

    float *gq, *gk, *gv, *ga;
    cudaGetSymbolAddress((void**)&gq, g_q);
    cudaGetSymbolAddress((void**)&gk, g_k);
    cudaGetSymbolAddress((void**)&gv, g_v);
    cudaGetSymbolAddress((void**)&ga, g_att);

    cudaFuncSetAttribute(attn_kernel,
                         cudaFuncAttributeMaxDynamicSharedMemorySize, ATT_SMEM);

    dim3 blk(256);
    const int M = B_ * T_;                 // 4096
    // Q/K/V projections
    gemm_tn<<<dim3(C_/128,  M/128), blk>>>(x, wq, gq, M, C_,  C_);
    gemm_tn<<<dim3(KVC/128, M/128), blk>>>(x, wk, gk, M, KVC, C_);
    gemm_tn<<<dim3(KVC/128, M/128), blk>>>(x, wv, gv, M, KVC, C_);
    // Attention
    attn_kernel<<<dim3(T_/64, QH, B_), blk, ATT_SMEM>>>();
    // Output projection
    gemm_tn<<<dim3(C_/128, M/128), blk>>>(ga, wo, out, M, C_, C_);
}

// round 2
// speedup vs baseline: 6.4667x; 6.4667x over previous
#include <cuda_runtime.h>
#include <math.h>

#define B_  2
#define T_  2048
#define C_  2048
#define QH  32
#define KVH 8
#define HD  64
#define NG  4
#define KVC (KVH*HD)   // 512

// Scratch (allocation-free rule: __device__ globals)
__device__ float g_q  [(size_t)B_*T_*C_];    // [b*T+t][h*64+d]
__device__ float g_k  [(size_t)B_*T_*KVC];
__device__ float g_v  [(size_t)B_*T_*KVC];
__device__ float g_att[(size_t)B_*T_*C_];

__device__ __forceinline__ unsigned f2tf(float x){
    unsigned r; asm("cvt.rna.tf32.f32 %0, %1;" : "=r"(r) : "f"(x)); return r;
}
__device__ __forceinline__ float tf2f(float x){       // round fp32 -> tf32, keep as float
    return __uint_as_float(f2tf(x));
}
__device__ __forceinline__ unsigned uf(float x){ return __float_as_uint(x); }

__device__ __forceinline__ void mma8(float* d, const unsigned* a, const unsigned* b){
    asm("mma.sync.aligned.m16n8k8.row.col.f32.tf32.tf32.f32 "
        "{%0,%1,%2,%3},{%4,%5,%6,%7},{%8,%9},{%0,%1,%2,%3};"
        : "+f"(d[0]), "+f"(d[1]), "+f"(d[2]), "+f"(d[3])
        : "r"(a[0]), "r"(a[1]), "r"(a[2]), "r"(a[3]), "r"(b[0]), "r"(b[1]));
}

// ---------------------------------------------------------------------------
// tf32 GEMM: C[M,N] = A[M,K] @ W[N,K]^T.  128x128x32 block tile, 4 warps,
// 64x64 warp tile (4 m-atoms x 8 n-atoms of m16n8k8).
// SMEM pad 36 floats/row -> bank = 4r+c = perfect lane permutation (no conflicts).
// ---------------------------------------------------------------------------
#define GPAD 36
__global__ __launch_bounds__(128) void gemm_tf32(const float* __restrict__ A,
                                                 const float* __restrict__ W,
                                                 float* __restrict__ Cm,
                                                 int M, int N, int K) {
    __shared__ float As[128*GPAD];
    __shared__ float Bs[128*GPAD];
    const int tid  = threadIdx.x;
    const int lane = tid & 31;
    const int wid  = tid >> 5;
    const int wm   = wid >> 1;      // 0..1
    const int wn   = wid & 1;       // 0..1
    const int m0   = blockIdx.y * 128;
    const int n0   = blockIdx.x * 128;

    float acc[4][8][4];
#pragma unroll
    for (int i = 0; i < 4; i++)
#pragma unroll
        for (int j = 0; j < 8; j++)
#pragma unroll
            for (int c = 0; c < 4; c++) acc[i][j][c] = 0.f;

    const float* Ab = A + (size_t)m0 * K;
    const float* Wb = W + (size_t)n0 * K;

    float4 ra[8], rb[8];
#pragma unroll
    for (int i = 0; i < 8; i++) {
        int lin = tid + i*128;
        ra[i] = *(const float4*)(Ab + (size_t)(lin>>3)*K + ((lin&7)<<2));
        rb[i] = *(const float4*)(Wb + (size_t)(lin>>3)*K + ((lin&7)<<2));
    }

    for (int k0 = 0; k0 < K; k0 += 32) {
        // store prefetched tile (converted to tf32)
#pragma unroll
        for (int i = 0; i < 8; i++) {
            int lin = tid + i*128;
            int row = lin >> 3, c = (lin&7) << 2;
            float* da = &As[row*GPAD + c];
            da[0]=tf2f(ra[i].x); da[1]=tf2f(ra[i].y); da[2]=tf2f(ra[i].z); da[3]=tf2f(ra[i].w);
            float* db = &Bs[row*GPAD + c];
            db[0]=tf2f(rb[i].x); db[1]=tf2f(rb[i].y); db[2]=tf2f(rb[i].z); db[3]=tf2f(rb[i].w);
        }
        __syncthreads();
        // prefetch next tile
        if (k0 + 32 < K) {
#pragma unroll
            for (int i = 0; i < 8; i++) {
                int lin = tid + i*128;
                ra[i] = *(const float4*)(Ab + (size_t)(lin>>3)*K + k0+32 + ((lin&7)<<2));
                rb[i] = *(const float4*)(Wb + (size_t)(lin>>3)*K + k0+32 + ((lin&7)<<2));
            }
        }
        // compute
#pragma unroll
        for (int ks = 0; ks < 4; ks++) {
            unsigned af[4][4];
#pragma unroll
            for (int ma = 0; ma < 4; ma++) {
                int base = (wm*64 + ma*16 + (lane>>2))*GPAD + ks*8 + (lane&3);
                af[ma][0] = uf(As[base]);
                af[ma][1] = uf(As[base + 8*GPAD]);
                af[ma][2] = uf(As[base + 4]);
                af[ma][3] = uf(As[base + 8*GPAD + 4]);
            }
#pragma unroll
            for (int na = 0; na < 8; na++) {
                int bb = (wn*64 + na*8 + (lane>>2))*GPAD + ks*8 + (lane&3);
                unsigned bf[2] = { uf(Bs[bb]), uf(Bs[bb+4]) };
#pragma unroll
                for (int ma = 0; ma < 4; ma++) mma8(acc[ma][na], af[ma], bf);
            }
        }
        __syncthreads();
    }

    // epilogue
#pragma unroll
    for (int ma = 0; ma < 4; ma++) {
        int row = m0 + wm*64 + ma*16 + (lane>>2);
#pragma unroll
        for (int na = 0; na < 8; na++) {
            int col = n0 + wn*64 + na*8 + ((lane&3)<<1);
            float2 v0; v0.x = acc[ma][na][0]; v0.y = acc[ma][na][1];
            float2 v1; v1.x = acc[ma][na][2]; v1.y = acc[ma][na][3];
            *(float2*)&Cm[(size_t)row*N + col]     = v0;
            *(float2*)&Cm[(size_t)(row+8)*N + col] = v1;
        }
    }
}

// ---------------------------------------------------------------------------
// tf32 flash attention: block = 128 q-rows x one (b,h); 4 warps, each 32 rows
// (2 m-atoms). K-tiles of 64. S = Q@K^T via mma (K row-major == col-frag B).
// P@V uses V rows stored with interleave pi(j)=(j>>1)+(j&1)*4 so the S/P
// C-fragment directly serves as the A-fragment.
// ---------------------------------------------------------------------------
#define QPAD 68   // bank map 4r+c: conflict-free for a-frag & K b-frag
#define VPAD 72   // bank map 8r+c: conflict-free for V b-frag
#define ATT_SMEM ((128*QPAD + 64*QPAD + 64*VPAD)*4)

__global__ __launch_bounds__(128) void attn_tf32() {
    extern __shared__ float sm[];
    float* Qs = sm;                          // [128][QPAD]
    float* Ks = sm + 128*QPAD;               // [64][QPAD]
    float* Vs = sm + 128*QPAD + 64*QPAD;     // [64][VPAD] (rows interleaved)

    const int qt = blockIdx.x, h = blockIdx.y, b = blockIdx.z;
    const int kvh = h >> 2;
    const int tid = threadIdx.x, lane = tid & 31, wid = tid >> 5;
    const int qbase = qt * 128;

    // load Q tile once (cvt to tf32)
#pragma unroll
    for (int i = 0; i < 16; i++) {
        int lin = tid + i*128;
        int row = lin >> 4, q = lin & 15;
        float4 v = *(const float4*)&g_q[(size_t)(b*T_ + qbase + row)*C_ + h*HD + q*4];
        float* d = &Qs[row*QPAD + q*4];
        d[0]=tf2f(v.x); d[1]=tf2f(v.y); d[2]=tf2f(v.z); d[3]=tf2f(v.w);
    }

    float sv[2][8][4];
    float oa[2][8][4];
    float mrow[2][2], lrow[2][2];
#pragma unroll
    for (int ma = 0; ma < 2; ma++) {
        mrow[ma][0] = mrow[ma][1] = -1e30f;
        lrow[ma][0] = lrow[ma][1] = 0.f;
#pragma unroll
        for (int na = 0; na < 8; na++)
#pragma unroll
            for (int c = 0; c < 4; c++) oa[ma][na][c] = 0.f;
    }

    const int nkt = 2*qt + 2;
    for (int kt = 0; kt < nkt; kt++) {
        __syncthreads();   // previous tile's frag reads done (also orders Q store)
        // load K and V tiles (64x64), cvt to tf32; V rows interleaved
#pragma unroll
        for (int i = 0; i < 8; i++) {
            int lin = tid + i*128;
            int row = lin >> 4, q = lin & 15;
            size_t gb = (size_t)(b*T_ + kt*64 + row)*KVC + kvh*HD + q*4;
            float4 kk = *(const float4*)&g_k[gb];
            float* dk = &Ks[row*QPAD + q*4];
            dk[0]=tf2f(kk.x); dk[1]=tf2f(kk.y); dk[2]=tf2f(kk.z); dk[3]=tf2f(kk.w);
            float4 vv = *(const float4*)&g_v[gb];
            int j = row & 7;
            int prow = (row & ~7) | ((j>>1) + ((j&1)<<2));
            float* dv = &Vs[prow*VPAD + q*4];
            dv[0]=tf2f(vv.x); dv[1]=tf2f(vv.y); dv[2]=tf2f(vv.z); dv[3]=tf2f(vv.w);
        }
        __syncthreads();

        // ---- S = Q @ K^T ----
#pragma unroll
        for (int ma = 0; ma < 2; ma++)
#pragma unroll
            for (int na = 0; na < 8; na++)
#pragma unroll
                for (int c = 0; c < 4; c++) sv[ma][na][c] = 0.f;

#pragma unroll
        for (int ks = 0; ks < 8; ks++) {
            unsigned aq[2][4];
#pragma unroll
            for (int ma = 0; ma < 2; ma++) {
                int base = (wid*32 + ma*16 + (lane>>2))*QPAD + ks*8 + (lane&3);
                aq[ma][0] = uf(Qs[base]);
                aq[ma][1] = uf(Qs[base + 8*QPAD]);
                aq[ma][2] = uf(Qs[base + 4]);
                aq[ma][3] = uf(Qs[base + 8*QPAD + 4]);
            }
#pragma unroll
            for (int na = 0; na < 8; na++) {
                int kb = (na*8 + (lane>>2))*QPAD + ks*8 + (lane&3);
                unsigned bk[2] = { uf(Ks[kb]), uf(Ks[kb+4]) };
#pragma unroll
                for (int ma = 0; ma < 2; ma++) mma8(sv[ma][na], aq[ma], bk);
            }
        }

        // ---- mask + online softmax (in registers) ----
        const bool need_mask = (kt >= 2*qt);
#pragma unroll
        for (int ma = 0; ma < 2; ma++) {
            int r0 = qbase + wid*32 + ma*16 + (lane>>2);
#pragma unroll
            for (int hh = 0; hh < 2; hh++) {
                int row = r0 + hh*8;
                float mt = -1e30f;
#pragma unroll
                for (int na = 0; na < 8; na++) {
#pragma unroll
                    for (int c = 0; c < 2; c++) {
                        float s = sv[ma][na][hh*2+c] * 0.125f;
                        if (need_mask) {
                            int colg = kt*64 + na*8 + ((lane&3)<<1) + c;
                            if (colg > row) s = -1e30f;
                        }
                        sv[ma][na][hh*2+c] = s;
                        mt = fmaxf(mt, s);
                    }
                }
                mt = fmaxf(mt, __shfl_xor_sync(0xffffffffu, mt, 1));
                mt = fmaxf(mt, __shfl_xor_sync(0xffffffffu, mt, 2));
                float mn   = fmaxf(mrow[ma][hh], mt);
                float corr = __expf(mrow[ma][hh] - mn);
                mrow[ma][hh] = mn;
                float ps = 0.f;
#pragma unroll
                for (int na = 0; na < 8; na++) {
#pragma unroll
                    for (int c = 0; c < 2; c++) {
                        float p = __expf(sv[ma][na][hh*2+c] - mn);
                        sv[ma][na][hh*2+c] = p;
                        ps += p;
                    }
                }
                ps += __shfl_xor_sync(0xffffffffu, ps, 1);
                ps += __shfl_xor_sync(0xffffffffu, ps, 2);
                lrow[ma][hh] = lrow[ma][hh]*corr + ps;
#pragma unroll
                for (int na = 0; na < 8; na++) {
                    oa[ma][na][hh*2]   *= corr;
                    oa[ma][na][hh*2+1] *= corr;
                }
            }
        }

        // ---- O += P @ V ----
#pragma unroll
        for (int ks = 0; ks < 8; ks++) {
            unsigned ap[2][4];
#pragma unroll
            for (int ma = 0; ma < 2; ma++) {
                ap[ma][0] = f2tf(sv[ma][ks][0]);  // (r,   k)
                ap[ma][1] = f2tf(sv[ma][ks][2]);  // (r+8, k)
                ap[ma][2] = f2tf(sv[ma][ks][1]);  // (r,   k+4)
                ap[ma][3] = f2tf(sv[ma][ks][3]);  // (r+8, k+4)
            }
#pragma unroll
            for (int na = 0; na < 8; na++) {
                int vb = (ks*8 + (lane&3))*VPAD + na*8 + (lane>>2);
                unsigned bv[2] = { uf(Vs[vb]), uf(Vs[vb + 4*VPAD]) };
#pragma unroll
                for (int ma = 0; ma < 2; ma++) mma8(oa[ma][na], ap[ma], bv);
            }
        }
    }

    // epilogue: normalize + store
#pragma unroll
    for (int ma = 0; ma < 2; ma++) {
#pragma unroll
        for (int hh = 0; hh < 2; hh++) {
            int row = qbase + wid*32 + ma*16 + (lane>>2) + hh*8;
            float inv = 1.f / lrow[ma][hh];
#pragma unroll
            for (int na = 0; na < 8; na++) {
                int col = h*HD + na*8 + ((lane&3)<<1);
                float2 o;
                o.x = oa[ma][na][hh*2]   * inv;
                o.y = oa[ma][na][hh*2+1] * inv;
                *(float2*)&g_att[(size_t)(b*T_ + row)*C_ + col] = o;
            }
        }
    }
}

// ---------------------------------------------------------------------------
extern "C" void kernel_launch(void* const* d_in, const int* in_sizes, int n_in,
                              void* d_out, int out_size) {
    const float* x  = (const float*)d_in[0];
    const float* wq = (const float*)d_in[1];
    const float* wk = (const float*)d_in[2];
    const float* wv = (const float*)d_in[3];
    const float* wo = (const float*)d_in[4];
    float* out = (float*)d_out;

    float *gq, *gk, *gv, *ga;
    cudaGetSymbolAddress((void**)&gq, g_q);
    cudaGetSymbolAddress((void**)&gk, g_k);
    cudaGetSymbolAddress((void**)&gv, g_v);
    cudaGetSymbolAddress((void**)&ga, g_att);

    cudaFuncSetAttribute(attn_tf32,
                         cudaFuncAttributeMaxDynamicSharedMemorySize, ATT_SMEM);

    const int M = B_ * T_;                 // 4096
    dim3 blk(128);
    gemm_tf32<<<dim3(C_/128,  M/128), blk>>>(x, wq, gq, M, C_,  C_);
    gemm_tf32<<<dim3(KVC/128, M/128), blk>>>(x, wk, gk, M, KVC, C_);
    gemm_tf32<<<dim3(KVC/128, M/128), blk>>>(x, wv, gv, M, KVC, C_);
    attn_tf32<<<dim3(T_/128, QH, B_), blk, ATT_SMEM>>>();
    gemm_tf32<<<dim3(C_/128, M/128), blk>>>(ga, wo, out, M, C_, C_);
}